// round 10
// baseline (speedup 1.0000x reference)
#include <cuda_runtime.h>

// End2End_7645041787474 — R10: R9 (19.2us) + pin logits batches {0,1}.
//
// Math collapse (R1): forward g == one_hot(argmax(logits+gumbel)); each output
// row is one W row (or zeros); nn_idx is that row's own index (or 0).
//
// L2 residency model (validated R7/R8/R9):
//   pinned(evict_last) 74MB  -> 19.2us   (R9, clean)
//   pinned 98.7MB            -> 25.1us   (R8, thrash; ~75% of 126MB L2 limit)
// R10 bisect: pin gumbel heavy rows + logits of batches 0,1 (~82.3MB < ~94.5MB
// est. set-aside limit). Steady DRAM stream 57.6 -> 49.4MB.

namespace {
constexpr int Bc  = 8;
constexpr int Lc  = 128;
constexpr int VFc = 32128;
constexpr int Vc  = 32100;
constexpr int Dc  = 768;
constexpr int NROWS = Bc * Lc;        // 1024
constexpr int NT  = 256;
constexpr int N8  = VFc / 8;          // 4016 8-float groups per row per stream
}

__device__ __forceinline__ unsigned long long pack_key(float v, int idx) {
    unsigned u = __float_as_uint(v);
    u = (u & 0x80000000u) ? ~u : (u | 0x80000000u);   // monotone float -> u32
    return ((unsigned long long)u << 32) | (unsigned)(~(unsigned)idx);
}

struct f8 { float v[8]; };

__device__ __forceinline__ f8 ld32_first(const float* p) {
    unsigned r0,r1,r2,r3,r4,r5,r6,r7;
    asm volatile("ld.global.nc.L2::evict_first.v8.b32 {%0,%1,%2,%3,%4,%5,%6,%7}, [%8];"
                 : "=r"(r0),"=r"(r1),"=r"(r2),"=r"(r3),
                   "=r"(r4),"=r"(r5),"=r"(r6),"=r"(r7) : "l"(p));
    f8 o;
    o.v[0]=__uint_as_float(r0); o.v[1]=__uint_as_float(r1);
    o.v[2]=__uint_as_float(r2); o.v[3]=__uint_as_float(r3);
    o.v[4]=__uint_as_float(r4); o.v[5]=__uint_as_float(r5);
    o.v[6]=__uint_as_float(r6); o.v[7]=__uint_as_float(r7);
    return o;
}
__device__ __forceinline__ f8 ld32_last(const float* p) {
    unsigned r0,r1,r2,r3,r4,r5,r6,r7;
    asm volatile("ld.global.nc.L2::evict_last.v8.b32 {%0,%1,%2,%3,%4,%5,%6,%7}, [%8];"
                 : "=r"(r0),"=r"(r1),"=r"(r2),"=r"(r3),
                   "=r"(r4),"=r"(r5),"=r"(r6),"=r"(r7) : "l"(p));
    f8 o;
    o.v[0]=__uint_as_float(r0); o.v[1]=__uint_as_float(r1);
    o.v[2]=__uint_as_float(r2); o.v[3]=__uint_as_float(r3);
    o.v[4]=__uint_as_float(r4); o.v[5]=__uint_as_float(r5);
    o.v[6]=__uint_as_float(r6); o.v[7]=__uint_as_float(r7);
    return o;
}
__device__ __forceinline__ void st32_stream(float* p, const f8& d) {
    asm volatile("st.global.cs.v8.b32 [%0], {%1,%2,%3,%4,%5,%6,%7,%8};"
                 :: "l"(p),
                    "r"(__float_as_uint(d.v[0])), "r"(__float_as_uint(d.v[1])),
                    "r"(__float_as_uint(d.v[2])), "r"(__float_as_uint(d.v[3])),
                    "r"(__float_as_uint(d.v[4])), "r"(__float_as_uint(d.v[5])),
                    "r"(__float_as_uint(d.v[6])), "r"(__float_as_uint(d.v[7])));
}

template <bool PIN_LOGITS>
__device__ __forceinline__ void argmax_body(const float* __restrict__ lp,
                                            const float* __restrict__ gp,
                                            int tid,
                                            unsigned long long& key_out)
{
    float vb[8];
    int   ib[8];
    #pragma unroll
    for (int e = 0; e < 8; e++) { vb[e] = -3.402823466e38f; ib[e] = 0x7fffffff; }

    #pragma unroll 2
    for (int j = tid; j < N8; j += NT) {
        const f8 a = PIN_LOGITS ? ld32_last(lp + (size_t)j * 8)
                                : ld32_first(lp + (size_t)j * 8);
        const f8 c = ld32_last(gp + (size_t)j * 8);   // gumbel: always pinned
        const int base = j << 3;
        #pragma unroll
        for (int e = 0; e < 8; e++) {
            const float z = a.v[e] + c.v[e];
            // strict '>' within ascending per-tracker scan: lowest index
            if (z > vb[e]) { vb[e] = z; ib[e] = base + e; }
        }
    }
    unsigned long long key = 0ULL;
    #pragma unroll
    for (int e = 0; e < 8; e++) {
        const unsigned long long k = pack_key(vb[e], ib[e]);
        if (k > key) key = k;
    }
    key_out = key;
}

__global__ __launch_bounds__(NT)
void fused_gsm_embed_nn(const float* __restrict__ logits,
                        const float* __restrict__ gumbel,
                        const float* __restrict__ wemb,
                        const int*   __restrict__ rwrt,
                        const int*   __restrict__ psg,
                        float*       __restrict__ out)
{
    // batch-interleaved mapping: heavy rows form a contiguous blockIdx prefix
    const int b   = blockIdx.x & 7;
    const int l   = blockIdx.x >> 3;
    const int row = (b << 7) | l;
    const int tid = threadIdx.x;

    __shared__ unsigned long long s_key[NT / 32];
    __shared__ int s_src, s_nn;
    __shared__ int s_red[NT];

    if (rwrt[row]) {
        const float* lp = logits + (size_t)row * VFc;
        const float* gp = gumbel + (size_t)row * VFc;

        unsigned long long key;
        if (b < 2) argmax_body<true >(lp, gp, tid, key);  // pin batches 0,1 logits
        else       argmax_body<false>(lp, gp, tid, key);  // stream logits

        #pragma unroll
        for (int off = 16; off > 0; off >>= 1) {
            const unsigned long long o = __shfl_down_sync(0xffffffffu, key, off);
            if (o > key) key = o;
        }
        if ((tid & 31) == 0) s_key[tid >> 5] = key;
        __syncthreads();
        if (tid == 0) {
            #pragma unroll
            for (int w = 1; w < NT / 32; w++)
                if (s_key[w] > key) key = s_key[w];
            const int g = (int)(~(unsigned)(key & 0xffffffffu));
            s_src = (g < Vc) ? g : -1;   // g >= V => zero row (g[..., :V])
            s_nn  = (g < Vc) ? g : 0;    // zero row => sims all 0 => argmax 0
        }
        __syncthreads();
    } else {
        // ---- psg path: len[b] = sum of prefix mask ----
        s_red[tid] = (tid < Lc) ? rwrt[b * Lc + tid] : 0;
        __syncthreads();
        #pragma unroll
        for (int s = NT / 2; s > 0; s >>= 1) {
            if (tid < s) s_red[tid] += s_red[tid + s];
            __syncthreads();
        }
        if (tid == 0) {
            const int len = s_red[0];
            const int idx = psg[b * Lc + (l - len)];
            s_src = idx;
            s_nn  = idx;
        }
        __syncthreads();
    }

    // ---- write embeds row: 96 threads x 32B; gather pinned, store streaming ----
    const int src = s_src;
    float* orow = out + (size_t)row * Dc;
    if (tid < Dc / 8) {               // 96 threads
        f8 d;
        if (src >= 0) {
            d = ld32_last(wemb + (size_t)src * Dc + tid * 8);   // reused per replay: pin
        } else {
            #pragma unroll
            for (int e = 0; e < 8; e++) d.v[e] = 0.f;
        }
        st32_stream(orow + tid * 8, d);   // output: evict-first, don't pollute L2
    }
    if (tid == 0)
        out[(size_t)NROWS * Dc + row] = (float)s_nn;
}

extern "C" void kernel_launch(void* const* d_in, const int* in_sizes, int n_in,
                              void* d_out, int out_size) {
    const float* logits = (const float*)d_in[0];
    const float* gumbel = (const float*)d_in[1];
    const float* wemb   = (const float*)d_in[2];
    const int*   rwrt   = (const int*)d_in[3];
    const int*   psg    = (const int*)d_in[4];
    float*       out    = (float*)d_out;

    fused_gsm_embed_nn<<<NROWS, NT>>>(logits, gumbel, wemb, rwrt, psg, out);
}